// round 10
// baseline (speedup 1.0000x reference)
#include <cuda_runtime.h>

#define NN 20000
#define BB 64
#define EE 1280000
#define TNB 625    // NN / 32

// Scratch (allocation-free). Globals start zeroed; scan_kernel restores
// g_count's zero-invariant every launch for graph replay.
__device__ __align__(16) float g_xT[NN * BB];   // xT[n*64 + b]
__device__ int  g_count[NN];
__device__ int  g_off[NN + 1];
__device__ int  g_cursor[NN];
__device__ __align__(16) int2 g_edge[EE];       // dst-binned (src, adj*w)

// K1: smem-tiled transpose x[B,N] -> xT[N,B] (R6 measured-best config).
__global__ void __launch_bounds__(512)
prep_kernel(const float* __restrict__ x) {
    __shared__ float t[32][65];
    int tid = threadIdx.x;
    int n0 = blockIdx.x * 32;
    const float4* x4 = (const float4*)x;
    {
        int b = tid >> 3, q = tid & 7;
        float4 v = x4[b * (NN / 4) + (n0 >> 2) + q];
        int nc = 4 * q;
        t[nc + 0][b] = v.x;  t[nc + 1][b] = v.y;
        t[nc + 2][b] = v.z;  t[nc + 3][b] = v.w;
    }
    __syncthreads();
    {
        float4* xT4 = (float4*)g_xT;
        int nc = tid >> 4, bq = tid & 15;
        int n = n0 + nc;
        float4 v;
        v.x = t[nc][4 * bq + 0];  v.y = t[nc][4 * bq + 1];
        v.z = t[nc][4 * bq + 2];  v.w = t[nc][4 * bq + 3];
        xT4[n * 16 + bq] = v;
    }
}

// K2: dst histogram, x4-vectorized (needs g_count==0; scan restores it).
__global__ void hist_kernel(const int* __restrict__ dst) {
    int i = blockIdx.x * blockDim.x + threadIdx.x;   // 625*512*4 = EE
    int4 d = ((const int4*)dst)[i];
    atomicAdd(&g_count[d.x], 1);
    atomicAdd(&g_count[d.y], 1);
    atomicAdd(&g_count[d.z], 1);
    atomicAdd(&g_count[d.w], 1);
}

// K3: single-block exclusive scan -> g_off/g_cursor; zeroes g_count.
__global__ void scan_kernel() {
    const int PER = 20;                 // 1024*20 >= NN
    __shared__ int wsum[32];
    int tid = threadIdx.x, lane = tid & 31, wid = tid >> 5;
    int base = tid * PER;
    int local[PER];
    int sum = 0;
    #pragma unroll
    for (int i = 0; i < PER; i++) {
        int idx = base + i;
        int c = (idx < NN) ? g_count[idx] : 0;
        local[i] = sum;
        sum += c;
    }
    int v = sum;
    #pragma unroll
    for (int o = 1; o < 32; o <<= 1) {
        int nv = __shfl_up_sync(0xffffffffu, v, o);
        if (lane >= o) v += nv;
    }
    if (lane == 31) wsum[wid] = v;
    __syncthreads();
    if (wid == 0) {
        int s = wsum[lane];
        #pragma unroll
        for (int o = 1; o < 32; o <<= 1) {
            int ns = __shfl_up_sync(0xffffffffu, s, o);
            if (lane >= o) s += ns;
        }
        wsum[lane] = s;
    }
    __syncthreads();
    int thread_excl = ((wid > 0) ? wsum[wid - 1] : 0) + (v - sum);
    #pragma unroll
    for (int i = 0; i < PER; i++) {
        int idx = base + i;
        if (idx < NN) {
            int o = thread_excl + local[i];
            g_off[idx]    = o;
            g_cursor[idx] = o;
            g_count[idx]  = 0;          // restore zero-invariant for replay
        }
    }
    if (tid == 0) g_off[NN] = EE;
}

// K4: bin edges into dst order, x4-vectorized metadata loads (MLP=4).
__global__ void bin_kernel(const float* __restrict__ adj,
                           const float* __restrict__ w,
                           const int* __restrict__ src,
                           const int* __restrict__ dst) {
    int i = blockIdx.x * blockDim.x + threadIdx.x;   // 625*512*4 = EE
    int4   d = ((const int4*)dst)[i];
    int4   s = ((const int4*)src)[i];
    float4 a = ((const float4*)adj)[i];
    float4 ww = ((const float4*)w)[i];
    int p0 = atomicAdd(&g_cursor[d.x], 1);
    int p1 = atomicAdd(&g_cursor[d.y], 1);
    int p2 = atomicAdd(&g_cursor[d.z], 1);
    int p3 = atomicAdd(&g_cursor[d.w], 1);
    g_edge[p0] = make_int2(s.x, __float_as_int(a.x * ww.x));
    g_edge[p1] = make_int2(s.y, __float_as_int(a.y * ww.y));
    g_edge[p2] = make_int2(s.z, __float_as_int(a.z * ww.z));
    g_edge[p3] = make_int2(s.w, __float_as_int(a.w * ww.w));
}

// K5: CSR SpMM, warp-per-node, LDS-broadcast edge pairs (no SHFL chain,
// no atomics), fused epilogue with coalesced output rows.
// Block = 16 consecutive nodes; lane holds cols {2*lane, 2*lane+1}.
__global__ void __launch_bounds__(512)
spmm_kernel(const float* __restrict__ x,
            const float* __restrict__ self_w,
            const float* __restrict__ bias,
            float* __restrict__ out) {
    __shared__ int2  pairs[16][32];
    __shared__ float so[64][17];       // [b][node_in_block], padded
    __shared__ float s_sl[16], s_bias[16];
    int tid = threadIdx.x, lane = tid & 31, wid = tid >> 5;
    int n0 = blockIdx.x * 16;
    int n  = n0 + wid;

    if (tid < 16) {
        int nn = n0 + tid;
        s_sl[tid]   = x[nn] * self_w[nn];  // x[0,n] — faithful reference quirk
        s_bias[tid] = bias[nn];
    }

    int beg = g_off[n], end = g_off[n + 1];
    float2 acc = make_float2(0.f, 0.f);
    const float2* xT2 = (const float2*)g_xT;

    for (int base = beg; base < end; base += 32) {
        int idx = base + lane;
        int2 pr = (idx < end) ? g_edge[idx] : make_int2(0, 0);  // v=0 pad
        pairs[wid][lane] = pr;
        __syncwarp();
        int cnt = min(32, end - base);
        if (cnt == 32) {
            #pragma unroll
            for (int k = 0; k < 32; k++) {
                int2 p = pairs[wid][k];               // LDS.64 broadcast
                float2 xv = xT2[p.x * 32 + lane];     // coalesced L2-hit
                float v = __int_as_float(p.y);
                acc.x = fmaf(v, xv.x, acc.x);
                acc.y = fmaf(v, xv.y, acc.y);
            }
        } else {
            for (int k = 0; k < cnt; k++) {
                int2 p = pairs[wid][k];
                float2 xv = xT2[p.x * 32 + lane];
                float v = __int_as_float(p.y);
                acc.x = fmaf(v, xv.x, acc.x);
                acc.y = fmaf(v, xv.y, acc.y);
            }
        }
        __syncwarp();
    }

    so[2 * lane][wid]     = acc.x;
    so[2 * lane + 1][wid] = acc.y;
    __syncthreads();

    // Epilogue: 64 b-rows x 16 nodes; coalesced 64B row segments.
    for (int i = tid; i < 64 * 16; i += 512) {
        int b = i >> 4, j = i & 15;
        float vv = fmaf(so[b][j], s_sl[j], s_bias[j]);
        out[b * NN + n0 + j] = fmaxf(vv, 0.f);
    }
}

extern "C" void kernel_launch(void* const* d_in, const int* in_sizes, int n_in,
                              void* d_out, int out_size) {
    const float* x      = (const float*)d_in[0];
    const float* adj    = (const float*)d_in[1];
    const float* w      = (const float*)d_in[2];
    const float* self_w = (const float*)d_in[3];
    const float* bias   = (const float*)d_in[4];
    const int*   src    = (const int*)d_in[5];
    const int*   dst    = (const int*)d_in[6];
    float* out = (float*)d_out;

    prep_kernel<<<TNB, 512>>>(x);
    hist_kernel<<<TNB, 512>>>(dst);
    scan_kernel<<<1, 1024>>>();
    bin_kernel<<<TNB, 512>>>(adj, w, src, dst);
    spmm_kernel<<<NN / 16, 512>>>(x, self_w, bias, out);
}

// round 11
// speedup vs baseline: 1.6648x; 1.6648x over previous
#include <cuda_runtime.h>

#define NN 20000
#define BB 64
#define EE 1280000
#define TNB 625    // NN / 32 (exact)

// Scratch (allocation-free per rules).
__device__ __align__(16) float g_xT[NN * BB];    // xT[n*64 + b]
__device__ __align__(16) float g_accT[NN * BB];  // accT[n*64 + b]

// K1: smem-tiled transpose x[B,N] -> xT[N,B] + zero accT (R6 measured-best:
// 625 blocks x 512 threads, one float4 item per thread per phase).
__global__ void __launch_bounds__(512)
prep_kernel(const float* __restrict__ x) {
    __shared__ float t[32][65];
    int tid = threadIdx.x;
    int n0 = blockIdx.x * 32;
    const float4* x4 = (const float4*)x;
    {
        int b = tid >> 3, q = tid & 7;
        float4 v = x4[b * (NN / 4) + (n0 >> 2) + q];
        int nc = 4 * q;
        t[nc + 0][b] = v.x;  t[nc + 1][b] = v.y;
        t[nc + 2][b] = v.z;  t[nc + 3][b] = v.w;
    }
    __syncthreads();
    {
        float4* xT4  = (float4*)g_xT;
        float4* acc4 = (float4*)g_accT;
        int nc = tid >> 4, bq = tid & 15;
        int n = n0 + nc;
        float4 v;
        v.x = t[nc][4 * bq + 0];  v.y = t[nc][4 * bq + 1];
        v.z = t[nc][4 * bq + 2];  v.w = t[nc][4 * bq + 3];
        xT4[n * 16 + bq]  = v;
        acc4[n * 16 + bq] = make_float4(0.f, 0.f, 0.f, 0.f);
    }
}

// K2: edge scatter, half-warp per edge (at the LTS byte cap). PDL secondary:
// the metadata prefix (src/dst/adj/w — pure inputs) runs BEFORE prep
// completes; cudaGridDependencySynchronize() gates the xT/accT section.
__global__ void scatter_kernel(const float* __restrict__ adj,
                               const float* __restrict__ w,
                               const int* __restrict__ src,
                               const int* __restrict__ dst) {
    int g = (blockIdx.x * blockDim.x + threadIdx.x) >> 5;  // warp id
    int lane = threadIdx.x & 31;
    int e = g * 32 + lane;

    // ---- independent prefix: overlaps with prep under PDL ----
    int   s = src[e];
    int   d = dst[e];
    float v = adj[e] * w[e];

    // wait for prep's grid (xT written, accT zeroed, all visible)
    cudaGridDependencySynchronize();

    int half = lane >> 4;
    int ll   = lane & 15;
    const float4* xT4 = (const float4*)g_xT;

    #pragma unroll 1
    for (int j = 0; j < 16; j++) {
        int sel = 2 * j + half;
        int   sj = __shfl_sync(0xffffffffu, s, sel);
        int   dj = __shfl_sync(0xffffffffu, d, sel);
        float vj = __shfl_sync(0xffffffffu, v, sel);

        float4 xv = xT4[sj * 16 + ll];           // LDG.128, coalesced, L2-hit
        float4 r;
        r.x = vj * xv.x;  r.y = vj * xv.y;
        r.z = vj * xv.z;  r.w = vj * xv.w;

        float* accp = &g_accT[dj * 64 + 4 * ll]; // 16B-aligned
        asm volatile("red.global.add.v4.f32 [%0], {%1, %2, %3, %4};"
                     :: "l"(accp), "f"(r.x), "f"(r.y), "f"(r.z), "f"(r.w)
                     : "memory");
    }
}

// K3: epilogue (R6 measured-best shape). PDL secondary: per-n scalar loads
// (x, self_w, bias — pure inputs) prefixed before the accT-dependent part.
__global__ void __launch_bounds__(512)
epilogue_kernel(const float* __restrict__ x,
                const float* __restrict__ self_w,
                const float* __restrict__ bias,
                float* __restrict__ out) {
    __shared__ float tile[32][65];
    __shared__ float s_sl[32];
    __shared__ float s_b[32];
    int tid = threadIdx.x;
    int n0 = blockIdx.x * 32;

    // ---- independent prefix: overlaps with scatter tail under PDL ----
    if (tid < 32) {
        int n = n0 + tid;
        s_sl[tid] = x[n] * self_w[n];   // x[0, n] — faithful reference quirk
        s_b[tid]  = bias[n];
    }

    cudaGridDependencySynchronize();    // wait for all atomics to land

    {
        const float4* acc4 = (const float4*)g_accT;
        int nc = tid >> 4, bq = tid & 15;
        int n = n0 + nc;
        float4 v = acc4[n * 16 + bq];
        tile[nc][4 * bq + 0] = v.x;
        tile[nc][4 * bq + 1] = v.y;
        tile[nc][4 * bq + 2] = v.z;
        tile[nc][4 * bq + 3] = v.w;
    }
    __syncthreads();
    {
        float4* out4 = (float4*)out;
        int b = tid >> 3, q = tid & 7;
        int nc = 4 * q;
        float4 r;
        r.x = fmaxf(fmaf(tile[nc + 0][b], s_sl[nc + 0], s_b[nc + 0]), 0.f);
        r.y = fmaxf(fmaf(tile[nc + 1][b], s_sl[nc + 1], s_b[nc + 1]), 0.f);
        r.z = fmaxf(fmaf(tile[nc + 2][b], s_sl[nc + 2], s_b[nc + 2]), 0.f);
        r.w = fmaxf(fmaf(tile[nc + 3][b], s_sl[nc + 3], s_b[nc + 3]), 0.f);
        out4[b * (NN / 4) + (n0 >> 2) + q] = r;
    }
}

extern "C" void kernel_launch(void* const* d_in, const int* in_sizes, int n_in,
                              void* d_out, int out_size) {
    const float* x      = (const float*)d_in[0];
    const float* adj    = (const float*)d_in[1];
    const float* w      = (const float*)d_in[2];
    const float* self_w = (const float*)d_in[3];
    const float* bias   = (const float*)d_in[4];
    const int*   src    = (const int*)d_in[5];
    const int*   dst    = (const int*)d_in[6];
    float* out = (float*)d_out;

    // K1: plain launch.
    prep_kernel<<<TNB, 512>>>(x);

    // K2 + K3: PDL secondaries (launch overlaps predecessor; device-side
    // cudaGridDependencySynchronize gates the dependent memory accesses).
    cudaLaunchAttribute attr;
    attr.id = cudaLaunchAttributeProgrammaticStreamSerialization;
    attr.val.programmaticStreamSerializationAllowed = 1;

    {
        cudaLaunchConfig_t cfg = {};
        cfg.gridDim  = dim3(EE / 256);
        cfg.blockDim = dim3(256);
        cfg.attrs    = &attr;
        cfg.numAttrs = 1;
        cudaLaunchKernelEx(&cfg, scatter_kernel, adj, w, src, dst);
    }
    {
        cudaLaunchConfig_t cfg = {};
        cfg.gridDim  = dim3(TNB);
        cfg.blockDim = dim3(512);
        cfg.attrs    = &attr;
        cfg.numAttrs = 1;
        cudaLaunchKernelEx(&cfg, epilogue_kernel, x, self_w, bias, out);
    }
}